// round 4
// baseline (speedup 1.0000x reference)
#include <cuda_runtime.h>

typedef unsigned long long u64;

static constexpr int D = 1024;
static constexpr int K = 32;
static constexpr int NT = 128;       // threads per block (1 thread = 1 row)
static constexpr int TILE_R = 128;   // rows per block
static constexpr int DC = 128;       // d-chunk

__device__ float g_C[K * K];

__device__ __forceinline__ u64 pack2(float lo, float hi) {
    u64 r;
    asm("mov.b64 %0, {%1, %2};" : "=l"(r) : "f"(lo), "f"(hi));
    return r;
}
__device__ __forceinline__ float2 unpack2(u64 v) {
    float2 r;
    asm("mov.b64 {%0, %1}, %2;" : "=f"(r.x), "=f"(r.y) : "l"(v));
    return r;
}
__device__ __forceinline__ void ffma2(u64& d, u64 a, u64 b) {
    asm("fma.rn.f32x2 %0, %1, %2, %0;" : "+l"(d) : "l"(a), "l"(b));
}

// ---------- prep: G = V V^T, then C = (I+U)^{-1} diag(beta) ----------
__global__ void prep_kernel(const float* __restrict__ V) {
    __shared__ float sG[K * K];
    __shared__ float sbeta[K];
    int t = threadIdx.x;             // 1024 threads: one (k1,k2) pair each
    int k1 = t >> 5, k2 = t & 31;
    float s = 0.f;
    #pragma unroll 8
    for (int j = 0; j < D; j += 4) {
        float4 a = *(const float4*)(V + k1 * D + j);
        float4 b = *(const float4*)(V + k2 * D + j);
        s += a.x * b.x + a.y * b.y + a.z * b.z + a.w * b.w;
    }
    sG[k1 * K + k2] = s;
    __syncthreads();
    if (t < K) sbeta[t] = 1.f / sG[t * K + t];
    __syncthreads();
    if (t < K) {
        float x[K];
        int c = t;
        for (int j = 0; j < K; j++) x[j] = 0.f;
        x[c] = 1.f;
        for (int j = c - 1; j >= 0; j--) {   // solve (I+U) x = e_c
            float s2 = 0.f;
            for (int m = j + 1; m <= c; m++) s2 += sbeta[j] * sG[j * K + m] * x[m];
            x[j] = -s2;
        }
        for (int j = 0; j < K; j++) g_C[j * K + c] = x[j] * sbeta[c];
    }
}

// ---------- fused: out = h - ((h V^T) C) V ----------
__global__ __launch_bounds__(NT, 4) void fused_kernel(
    const float* __restrict__ H, const float* __restrict__ V,
    float* __restrict__ OUT)
{
    // union buffer: phase A Vt[d][k] (DC x 36), phase B Vs[k][d] (K x 132)
    __shared__ float s_buf[DC * 36];
    __shared__ float s_C[K * K];

    const int t = threadIdx.x;
    const int row = blockIdx.x * TILE_R + t;
    const float* hrow = H + (size_t)row * D;

    for (int i = t; i < K * K; i += NT) s_C[i] = g_C[i];

    const int kl = t & 31;      // staging: lane -> k (stride-1 banks)
    const int gl = t >> 5;      // staging: quarter of the d-chunk

    // ================= Phase A: p[32] = h_row . V^T =================
    u64 acc[16];
    #pragma unroll
    for (int i = 0; i < 16; i++) acc[i] = 0ULL;

    for (int dc = 0; dc < D; dc += DC) {
        __syncthreads();
        #pragma unroll
        for (int f = 0; f < 8; f++) {        // stage Vt[d][k], transposed
            int f4 = gl * 8 + f;
            float4 vv = *(const float4*)(V + kl * D + dc + f4 * 4);
            s_buf[(f4 * 4 + 0) * 36 + kl] = vv.x;
            s_buf[(f4 * 4 + 1) * 36 + kl] = vv.y;
            s_buf[(f4 * 4 + 2) * 36 + kl] = vv.z;
            s_buf[(f4 * 4 + 3) * 36 + kl] = vv.w;
        }
        __syncthreads();
        #pragma unroll
        for (int q = 0; q < 4; q++) {         // 4 quarter-batches of 32 floats
            float4 hb[8];                     // 8 float4 = 32 floats, MLP=8
            #pragma unroll
            for (int i = 0; i < 8; i++)
                hb[i] = *(const float4*)(hrow + dc + q * 32 + i * 4);
            #pragma unroll
            for (int i = 0; i < 8; i++) {
                const float* hs = (const float*)&hb[i];
                #pragma unroll
                for (int j = 0; j < 4; j++) {
                    u64 hh = pack2(hs[j], hs[j]);
                    const float* vtd = &s_buf[(q * 32 + i * 4 + j) * 36];
                    #pragma unroll
                    for (int kk = 0; kk < 8; kk++) {
                        float4 v4 = *(const float4*)(vtd + kk * 4);  // broadcast
                        const u64* vp = (const u64*)&v4;
                        ffma2(acc[kk * 2 + 0], hh, vp[0]);
                        ffma2(acc[kk * 2 + 1], hh, vp[1]);
                    }
                }
            }
        }
    }

    // ================= w = p . C, pack wp =================
    float p[K];
    #pragma unroll
    for (int i = 0; i < 16; i++) {
        float2 f = unpack2(acc[i]);
        p[2 * i] = f.x;
        p[2 * i + 1] = f.y;
    }
    u64 wacc[16];
    #pragma unroll
    for (int i = 0; i < 16; i++) wacc[i] = 0ULL;
    #pragma unroll
    for (int j = 0; j < K; j++) {
        u64 pj = pack2(p[j], p[j]);
        #pragma unroll
        for (int kk = 0; kk < 8; kk++) {
            float4 c4 = *(const float4*)(&s_C[j * K + kk * 4]);
            const u64* cp = (const u64*)&c4;
            ffma2(wacc[kk * 2 + 0], pj, cp[0]);
            ffma2(wacc[kk * 2 + 1], pj, cp[1]);
        }
    }
    u64 wp[K];
    #pragma unroll
    for (int i = 0; i < 16; i++) {
        float2 f = unpack2(wacc[i]);
        wp[2 * i] = pack2(f.x, f.x);
        wp[2 * i + 1] = pack2(f.y, f.y);
    }

    // ================= Phase B: out_row = h_row - w . V =================
    for (int dc = 0; dc < D; dc += DC) {
        __syncthreads();
        #pragma unroll
        for (int f = 0; f < 8; f++) {         // stage Vs[k][d], natural layout
            int f4 = gl * 8 + f;
            *(float4*)(&s_buf[kl * 132 + f4 * 4]) =
                *(const float4*)(V + kl * D + dc + f4 * 4);
        }
        __syncthreads();
        #pragma unroll 4
        for (int d4 = 0; d4 < DC / 4; d4++) {
            float4 hv = *(const float4*)(hrow + dc + d4 * 4);  // hoisted early
            u64 c0 = 0ULL, c1 = 0ULL;
            #pragma unroll
            for (int kk = 0; kk < K; kk++) {
                float4 v4 = *(const float4*)(&s_buf[kk * 132 + d4 * 4]);  // broadcast
                const u64* vp = (const u64*)&v4;
                ffma2(c0, wp[kk], vp[0]);
                ffma2(c1, wp[kk], vp[1]);
            }
            float2 lo = unpack2(c0);
            float2 hi = unpack2(c1);
            float4 o;
            o.x = hv.x - lo.x;
            o.y = hv.y - lo.y;
            o.z = hv.z - hi.x;
            o.w = hv.w - hi.y;
            *(float4*)(OUT + (size_t)row * D + dc + d4 * 4) = o;
        }
    }
}

extern "C" void kernel_launch(void* const* d_in, const int* in_sizes, int n_in,
                              void* d_out, int out_size) {
    const float* H = (const float*)d_in[0];   // node_feat [65536, 1024]
    const float* V = (const float*)d_in[1];   // V [32, 1024]
    float* OUT = (float*)d_out;
    const int N = in_sizes[0] / D;

    prep_kernel<<<1, 1024>>>(V);
    fused_kernel<<<N / TILE_R, NT>>>(H, V, OUT);
}

// round 5
// speedup vs baseline: 1.3334x; 1.3334x over previous
#include <cuda_runtime.h>

typedef unsigned long long u64;

static constexpr int D = 1024;
static constexpr int K = 32;
static constexpr int NT = 256;       // threads per block
static constexpr int TILE_R = 128;   // rows per block
static constexpr int DC = 32;        // d-chunk

__device__ float g_C[K * K];

__device__ __forceinline__ u64 pack2(float lo, float hi) {
    u64 r;
    asm("mov.b64 %0, {%1, %2};" : "=l"(r) : "f"(lo), "f"(hi));
    return r;
}
__device__ __forceinline__ float2 unpack2(u64 v) {
    float2 r;
    asm("mov.b64 {%0, %1}, %2;" : "=f"(r.x), "=f"(r.y) : "l"(v));
    return r;
}
__device__ __forceinline__ void ffma2(u64& d, u64 a, u64 b) {
    asm("fma.rn.f32x2 %0, %1, %2, %0;" : "+l"(d) : "l"(a), "l"(b));
}

// ---------- prep: G = V V^T, then C = (I+U)^{-1} diag(beta) ----------
__global__ void prep_kernel(const float* __restrict__ V) {
    __shared__ float sG[K * K];
    __shared__ float sbeta[K];
    int t = threadIdx.x;             // 1024 threads: one (k1,k2) pair each
    int k1 = t >> 5, k2 = t & 31;
    float s = 0.f;
    #pragma unroll 8
    for (int j = 0; j < D; j += 4) {
        float4 a = *(const float4*)(V + k1 * D + j);
        float4 b = *(const float4*)(V + k2 * D + j);
        s += a.x * b.x + a.y * b.y + a.z * b.z + a.w * b.w;
    }
    sG[k1 * K + k2] = s;
    __syncthreads();
    if (t < K) sbeta[t] = 1.f / sG[t * K + t];
    __syncthreads();
    if (t < K) {
        float x[K];
        int c = t;
        for (int j = 0; j < K; j++) x[j] = 0.f;
        x[c] = 1.f;
        for (int j = c - 1; j >= 0; j--) {   // solve (I+U) x = e_c
            float s2 = 0.f;
            for (int m = j + 1; m <= c; m++) s2 += sbeta[j] * sG[j * K + m] * x[m];
            x[j] = -s2;
        }
        for (int j = 0; j < K; j++) g_C[j * K + c] = x[j] * sbeta[c];
    }
}

// ---------- fused: out = h - ((h V^T) C) V ----------
__global__ __launch_bounds__(NT, 2) void fused_kernel(
    const float* __restrict__ H, const float* __restrict__ V,
    float* __restrict__ OUT)
{
    __shared__ __align__(16) float Hs[TILE_R * 36];      // A: H tile; B: corr tile
    __shared__ __align__(16) float Vt[DC * 36];          // A: Vt[d][k]
    __shared__ __align__(16) float Vs[K * DC];           // B: Vs[k][d]
    __shared__ float Ps2[2 * TILE_R * 33];               // A partials (2 d-halves)
    __shared__ float Ws[TILE_R * 33];                    // W = P C
    __shared__ __align__(16) float sC[K * K];

    const int t = threadIdx.x;
    const int row0 = blockIdx.x * TILE_R;

    for (int i = t; i < K * K; i += NT) sC[i] = g_C[i];

    // ============ Phase A: P = H_tile @ V^T ============
    // thread = 2 rows (rqa, rqa+64) x 16 k (kqa half) x 16 d (dqa half)
    const int rqa = t & 63;
    const int dqa = (t >> 6) & 1;
    const int kqa = t >> 7;
    const int fr = t >> 3;           // f-pattern row base (staging)
    const int fc4 = t & 7;           // f-pattern float4 index
    const int vk = t >> 3;           // V staging: k (t<256 -> vk<32)

    u64 acc[16];                     // [row j][k-pair]: acc[j*8 + kp]
    #pragma unroll
    for (int i = 0; i < 16; i++) acc[i] = 0ULL;

    for (int dc = 0; dc < D; dc += DC) {
        __syncthreads();
        #pragma unroll
        for (int i = 0; i < 4; i++) {        // stage Hs[r][d], coalesced
            int r = i * 32 + fr;
            float4 hv = *(const float4*)(H + (size_t)(row0 + r) * D + dc + fc4 * 4);
            *(float4*)(&Hs[r * 36 + fc4 * 4]) = hv;
        }
        {                                    // stage Vt[d][k], transposed scatter
            float4 vv = *(const float4*)(V + vk * D + dc + fc4 * 4);
            Vt[(fc4 * 4 + 0) * 36 + vk] = vv.x;
            Vt[(fc4 * 4 + 1) * 36 + vk] = vv.y;
            Vt[(fc4 * 4 + 2) * 36 + vk] = vv.z;
            Vt[(fc4 * 4 + 3) * 36 + vk] = vv.w;
        }
        __syncthreads();
        #pragma unroll
        for (int d4 = 0; d4 < 4; d4++) {
            int d0 = dqa * 16 + d4 * 4;
            float4 h0 = *(const float4*)(&Hs[rqa * 36 + d0]);
            float4 h1 = *(const float4*)(&Hs[(rqa + 64) * 36 + d0]);
            const float* h0s = (const float*)&h0;
            const float* h1s = (const float*)&h1;
            #pragma unroll
            for (int j = 0; j < 4; j++) {
                u64 hh0 = pack2(h0s[j], h0s[j]);
                u64 hh1 = pack2(h1s[j], h1s[j]);
                const float* vrow = &Vt[(d0 + j) * 36 + kqa * 16];
                #pragma unroll
                for (int q = 0; q < 4; q++) {
                    float4 v4 = *(const float4*)(vrow + q * 4);
                    const u64* vp = (const u64*)&v4;
                    ffma2(acc[q * 2 + 0], hh0, vp[0]);
                    ffma2(acc[q * 2 + 1], hh0, vp[1]);
                    ffma2(acc[8 + q * 2 + 0], hh1, vp[0]);
                    ffma2(acc[8 + q * 2 + 1], hh1, vp[1]);
                }
            }
        }
    }
    __syncthreads();
    #pragma unroll
    for (int j = 0; j < 2; j++) {            // write partials (dqa half)
        int r = rqa + 64 * j;
        float* pr = &Ps2[(dqa * TILE_R + r) * 33 + kqa * 16];
        #pragma unroll
        for (int kp = 0; kp < 8; kp++) {
            float2 f = unpack2(acc[j * 8 + kp]);
            pr[kp * 2] = f.x;
            pr[kp * 2 + 1] = f.y;
        }
    }
    __syncthreads();

    // ============ W = (P0+P1) @ C ============
    {
        int rt = t & 127, kh = t >> 7;       // row, k-half
        float w[16];
        #pragma unroll
        for (int c = 0; c < 16; c++) w[c] = 0.f;
        for (int j = 0; j < K; j++) {
            float pj = Ps2[rt * 33 + j] + Ps2[(TILE_R + rt) * 33 + j];
            #pragma unroll
            for (int c4 = 0; c4 < 4; c4++) {
                float4 cv = *(const float4*)(&sC[j * K + kh * 16 + c4 * 4]);
                w[c4 * 4 + 0] += pj * cv.x;
                w[c4 * 4 + 1] += pj * cv.y;
                w[c4 * 4 + 2] += pj * cv.z;
                w[c4 * 4 + 3] += pj * cv.w;
            }
        }
        #pragma unroll
        for (int c = 0; c < 16; c++) Ws[rt * 33 + kh * 16 + c] = w[c];
    }
    __syncthreads();

    // ============ Phase B: out = h - W @ V ============
    const int rqb = t >> 2;      // 0..63 -> rows rqb, rqb+64
    const int dqb = t & 3;       // d = dqb*8 .. +7
    float w0[K], w1[K];
    #pragma unroll
    for (int k = 0; k < K; k++) {
        w0[k] = Ws[rqb * 33 + k];
        w1[k] = Ws[(rqb + 64) * 33 + k];
    }

    for (int dc = 0; dc < D; dc += DC) {
        __syncthreads();
        {                                    // stage Vs[k][d], natural
            *(float4*)(&Vs[vk * DC + fc4 * 4]) =
                *(const float4*)(V + vk * D + dc + fc4 * 4);
        }
        __syncthreads();
        u64 a2[2][4];
        #pragma unroll
        for (int j = 0; j < 2; j++)
            #pragma unroll
            for (int i = 0; i < 4; i++) a2[j][i] = 0ULL;
        #pragma unroll
        for (int k = 0; k < K; k++) {
            float4 va = *(const float4*)(&Vs[k * DC + dqb * 8]);
            float4 vb = *(const float4*)(&Vs[k * DC + dqb * 8 + 4]);
            const u64* vpa = (const u64*)&va;
            const u64* vpb = (const u64*)&vb;
            u64 ww0 = pack2(w0[k], w0[k]);
            u64 ww1 = pack2(w1[k], w1[k]);
            ffma2(a2[0][0], ww0, vpa[0]); ffma2(a2[0][1], ww0, vpa[1]);
            ffma2(a2[0][2], ww0, vpb[0]); ffma2(a2[0][3], ww0, vpb[1]);
            ffma2(a2[1][0], ww1, vpa[0]); ffma2(a2[1][1], ww1, vpa[1]);
            ffma2(a2[1][2], ww1, vpb[0]); ffma2(a2[1][3], ww1, vpb[1]);
        }
        #pragma unroll
        for (int j = 0; j < 2; j++) {        // corr -> Hs (stride 36)
            int r = rqb + 64 * j;
            float2 p0 = unpack2(a2[j][0]);
            float2 p1 = unpack2(a2[j][1]);
            float2 p2 = unpack2(a2[j][2]);
            float2 p3 = unpack2(a2[j][3]);
            float4 ca = {p0.x, p0.y, p1.x, p1.y};
            float4 cb = {p2.x, p2.y, p3.x, p3.y};
            *(float4*)(&Hs[r * 36 + dqb * 8]) = ca;
            *(float4*)(&Hs[r * 36 + dqb * 8 + 4]) = cb;
        }
        __syncthreads();
        #pragma unroll
        for (int i = 0; i < 4; i++) {        // epilogue, fully coalesced
            int r = i * 32 + fr;
            float4 hv = *(const float4*)(H + (size_t)(row0 + r) * D + dc + fc4 * 4);
            float4 cr = *(const float4*)(&Hs[r * 36 + fc4 * 4]);
            float4 o = {hv.x - cr.x, hv.y - cr.y, hv.z - cr.z, hv.w - cr.w};
            *(float4*)(OUT + (size_t)(row0 + r) * D + dc + fc4 * 4) = o;
        }
    }
}

extern "C" void kernel_launch(void* const* d_in, const int* in_sizes, int n_in,
                              void* d_out, int out_size) {
    const float* H = (const float*)d_in[0];   // node_feat [65536, 1024]
    const float* V = (const float*)d_in[1];   // V [32, 1024]
    float* OUT = (float*)d_out;
    const int N = in_sizes[0] / D;

    prep_kernel<<<1, 1024>>>(V);
    fused_kernel<<<N / TILE_R, NT>>>(H, V, OUT);
}

// round 6
// speedup vs baseline: 1.8464x; 1.3848x over previous
#include <cuda_runtime.h>

typedef unsigned long long u64;

static constexpr int D = 1024;
static constexpr int K = 32;
static constexpr int NT = 256;
static constexpr int TILE_R = 128;
static constexpr int DC = 32;

__device__ float g_G[K * K];
__device__ float g_C[K * K];

__device__ __forceinline__ u64 pack2(float lo, float hi) {
    u64 r;
    asm("mov.b64 %0, {%1, %2};" : "=l"(r) : "f"(lo), "f"(hi));
    return r;
}
__device__ __forceinline__ float2 unpack2(u64 v) {
    float2 r;
    asm("mov.b64 {%0, %1}, %2;" : "=f"(r.x), "=f"(r.y) : "l"(v));
    return r;
}
__device__ __forceinline__ void ffma2(u64& d, u64 a, u64 b) {
    asm("fma.rn.f32x2 %0, %1, %2, %0;" : "+l"(d) : "l"(a), "l"(b));
}

// ---------------- G = V V^T (32 blocks, fast) ----------------
__global__ void gram_kernel(const float* __restrict__ V) {
    int k1 = blockIdx.x;
    int w = threadIdx.x >> 5;
    int lane = threadIdx.x & 31;
    #pragma unroll
    for (int i = 0; i < 4; i++) {
        int k2 = w * 4 + i;
        float s = 0.f;
        #pragma unroll
        for (int j = 0; j < D; j += 128) {
            float4 a = *(const float4*)(V + k1 * D + j + lane * 4);
            float4 b = *(const float4*)(V + k2 * D + j + lane * 4);
            s += a.x * b.x + a.y * b.y + a.z * b.z + a.w * b.w;
        }
        #pragma unroll
        for (int o = 16; o; o >>= 1) s += __shfl_down_sync(0xffffffffu, s, o);
        if (lane == 0) g_G[k1 * K + k2] = s;
    }
}

// ---------------- C = (I+U)^{-1} diag(beta) ----------------
__global__ void prepc_kernel() {
    __shared__ float G[K * K];
    __shared__ float beta[K];
    int t = threadIdx.x;
    for (int i = t; i < K * K; i += 32) G[i] = g_G[i];
    __syncwarp();
    beta[t] = 1.f / G[t * K + t];
    __syncwarp();
    float x[K];
    int c = t;
    for (int j = 0; j < K; j++) x[j] = 0.f;
    x[c] = 1.f;
    for (int j = c - 1; j >= 0; j--) {
        float s = 0.f;
        for (int m = j + 1; m <= c; m++) s += beta[j] * G[j * K + m] * x[m];
        x[j] = -s;
    }
    for (int j = 0; j < K; j++) g_C[j * K + c] = x[j] * beta[c];
}

// ---------------- fused: out = h - ((h V^T) C) V ----------------
__global__ __launch_bounds__(NT, 2) void fused_kernel(
    const float* __restrict__ H, const float* __restrict__ V,
    float* __restrict__ OUT)
{
    __shared__ __align__(16) float Hs[TILE_R * 36];  // A: swizzled stride-32; B: corr stride-36
    __shared__ __align__(16) float Vb[DC * 36];      // A: Vt[d][k] s36; B: Vs[k][d] s32
    __shared__ float Ps2[2 * TILE_R * 33];
    __shared__ float Ws[TILE_R * 33];
    __shared__ __align__(16) float sC[K * K];

    const int t = threadIdx.x;
    const int row0 = blockIdx.x * TILE_R;

    for (int i = t; i < K * K; i += NT) sC[i] = g_C[i];

    // phase-A thread tile: 4 rows x 16 k x 8 d
    const int rg = t & 31;           // rows rg+{0,32,64,96}
    const int kh = (t >> 5) & 1;     // k-half (16 k)
    const int dq = t >> 6;           // d-quarter (8 d)
    // staging ids
    const int fr = t >> 3;           // 0..31
    const int fc4 = t & 7;           // 0..7
    const int vk = t >> 3;           // 0..31

    u64 acc[4][8];
    #pragma unroll
    for (int j = 0; j < 4; j++)
        #pragma unroll
        for (int i = 0; i < 8; i++) acc[j][i] = 0ULL;

    for (int dc = 0; dc < D; dc += DC) {
        __syncthreads();
        #pragma unroll
        for (int i = 0; i < 4; i++) {           // stage Hs, XOR-swizzled stride 32
            int r = i * 32 + fr;
            float4 hv = *(const float4*)(H + (size_t)(row0 + r) * D + dc + fc4 * 4);
            *(float4*)(&Hs[r * 32 + ((fc4 ^ (r & 7)) << 2)]) = hv;
        }
        {                                       // stage Vt[d][k], stride 36
            float4 vv = *(const float4*)(V + vk * D + dc + fc4 * 4);
            Vb[(fc4 * 4 + 0) * 36 + vk] = vv.x;
            Vb[(fc4 * 4 + 1) * 36 + vk] = vv.y;
            Vb[(fc4 * 4 + 2) * 36 + vk] = vv.z;
            Vb[(fc4 * 4 + 3) * 36 + vk] = vv.w;
        }
        __syncthreads();
        #pragma unroll
        for (int d4 = 0; d4 < 2; d4++) {
            float4 hv[4];
            #pragma unroll
            for (int j = 0; j < 4; j++) {
                int r = rg + 32 * j;
                hv[j] = *(const float4*)(&Hs[r * 32 + (((dq * 2 + d4) ^ (r & 7)) << 2)]);
            }
            #pragma unroll
            for (int e = 0; e < 4; e++) {
                int d = dq * 8 + d4 * 4 + e;
                const float* vrow = &Vb[d * 36 + kh * 16];
                float4 v0 = *(const float4*)(vrow);
                float4 v1 = *(const float4*)(vrow + 4);
                float4 v2 = *(const float4*)(vrow + 8);
                float4 v3 = *(const float4*)(vrow + 12);
                const u64* p0 = (const u64*)&v0;
                const u64* p1 = (const u64*)&v1;
                const u64* p2 = (const u64*)&v2;
                const u64* p3 = (const u64*)&v3;
                #pragma unroll
                for (int j = 0; j < 4; j++) {
                    float he = ((const float*)&hv[j])[e];
                    u64 hh = pack2(he, he);
                    ffma2(acc[j][0], hh, p0[0]); ffma2(acc[j][1], hh, p0[1]);
                    ffma2(acc[j][2], hh, p1[0]); ffma2(acc[j][3], hh, p1[1]);
                    ffma2(acc[j][4], hh, p2[0]); ffma2(acc[j][5], hh, p2[1]);
                    ffma2(acc[j][6], hh, p3[0]); ffma2(acc[j][7], hh, p3[1]);
                }
            }
        }
    }

    // ---- partials: 4 d-quarters -> 2 slabs (two passes), then W = (P0+P1) C ----
    __syncthreads();
    if (dq < 2) {
        #pragma unroll
        for (int j = 0; j < 4; j++) {
            int r = rg + 32 * j;
            float* pr = &Ps2[(dq * TILE_R + r) * 33 + kh * 16];
            #pragma unroll
            for (int i = 0; i < 8; i++) {
                float2 f = unpack2(acc[j][i]);
                pr[2 * i] = f.x;
                pr[2 * i + 1] = f.y;
            }
        }
    }
    __syncthreads();
    if (dq >= 2) {
        #pragma unroll
        for (int j = 0; j < 4; j++) {
            int r = rg + 32 * j;
            float* pr = &Ps2[((dq - 2) * TILE_R + r) * 33 + kh * 16];
            #pragma unroll
            for (int i = 0; i < 8; i++) {
                float2 f = unpack2(acc[j][i]);
                pr[2 * i] += f.x;
                pr[2 * i + 1] += f.y;
            }
        }
    }
    __syncthreads();
    {
        int rt = t & 127, kh2 = t >> 7;
        float w[16];
        #pragma unroll
        for (int c = 0; c < 16; c++) w[c] = 0.f;
        #pragma unroll 4
        for (int j = 0; j < K; j++) {
            float pj = Ps2[rt * 33 + j] + Ps2[(TILE_R + rt) * 33 + j];
            #pragma unroll
            for (int c4 = 0; c4 < 4; c4++) {
                float4 cv = *(const float4*)(&sC[j * K + kh2 * 16 + c4 * 4]);
                w[c4 * 4 + 0] += pj * cv.x;
                w[c4 * 4 + 1] += pj * cv.y;
                w[c4 * 4 + 2] += pj * cv.z;
                w[c4 * 4 + 3] += pj * cv.w;
            }
        }
        #pragma unroll
        for (int c = 0; c < 16; c++) Ws[rt * 33 + kh2 * 16 + c] = w[c];
    }
    __syncthreads();

    // ---- Phase B: out = h - W V ----
    const int rqb = t >> 2;      // rows rqb, rqb+64
    const int dqb = t & 3;       // d = dqb*8 .. +7
    float w0[K], w1[K];
    #pragma unroll
    for (int k = 0; k < K; k++) {
        w0[k] = Ws[rqb * 33 + k];
        w1[k] = Ws[(rqb + 64) * 33 + k];
    }

    for (int dc = 0; dc < D; dc += DC) {
        __syncthreads();
        *(float4*)(&Vb[vk * 32 + fc4 * 4]) =
            *(const float4*)(V + vk * D + dc + fc4 * 4);
        __syncthreads();
        u64 a2[2][4];
        #pragma unroll
        for (int j = 0; j < 2; j++)
            #pragma unroll
            for (int i = 0; i < 4; i++) a2[j][i] = 0ULL;
        #pragma unroll
        for (int k = 0; k < K; k++) {
            float4 va = *(const float4*)(&Vb[k * 32 + dqb * 8]);
            float4 vb = *(const float4*)(&Vb[k * 32 + dqb * 8 + 4]);
            const u64* vpa = (const u64*)&va;
            const u64* vpb = (const u64*)&vb;
            u64 ww0 = pack2(w0[k], w0[k]);
            u64 ww1 = pack2(w1[k], w1[k]);
            ffma2(a2[0][0], ww0, vpa[0]); ffma2(a2[0][1], ww0, vpa[1]);
            ffma2(a2[0][2], ww0, vpb[0]); ffma2(a2[0][3], ww0, vpb[1]);
            ffma2(a2[1][0], ww1, vpa[0]); ffma2(a2[1][1], ww1, vpa[1]);
            ffma2(a2[1][2], ww1, vpb[0]); ffma2(a2[1][3], ww1, vpb[1]);
        }
        #pragma unroll
        for (int j = 0; j < 2; j++) {
            int r = rqb + 64 * j;
            float2 p0 = unpack2(a2[j][0]);
            float2 p1 = unpack2(a2[j][1]);
            float2 p2 = unpack2(a2[j][2]);
            float2 p3 = unpack2(a2[j][3]);
            float4 ca = {p0.x, p0.y, p1.x, p1.y};
            float4 cb = {p2.x, p2.y, p3.x, p3.y};
            *(float4*)(&Hs[r * 36 + dqb * 8]) = ca;
            *(float4*)(&Hs[r * 36 + dqb * 8 + 4]) = cb;
        }
        __syncthreads();
        #pragma unroll
        for (int i = 0; i < 4; i++) {
            int r = i * 32 + fr;
            float4 hv = *(const float4*)(H + (size_t)(row0 + r) * D + dc + fc4 * 4);
            float4 cr = *(const float4*)(&Hs[r * 36 + fc4 * 4]);
            float4 o = {hv.x - cr.x, hv.y - cr.y, hv.z - cr.z, hv.w - cr.w};
            *(float4*)(OUT + (size_t)(row0 + r) * D + dc + fc4 * 4) = o;
        }
    }
}

extern "C" void kernel_launch(void* const* d_in, const int* in_sizes, int n_in,
                              void* d_out, int out_size) {
    const float* H = (const float*)d_in[0];
    const float* V = (const float*)d_in[1];
    float* OUT = (float*)d_out;
    const int N = in_sizes[0] / D;

    gram_kernel<<<K, 256>>>(V);
    prepc_kernel<<<1, 32>>>();
    fused_kernel<<<N / TILE_R, NT>>>(H, V, OUT);
}

// round 7
// speedup vs baseline: 2.1588x; 1.1692x over previous
#include <cuda_runtime.h>

typedef unsigned long long u64;

static constexpr int D = 1024;
static constexpr int K = 32;
static constexpr int NT = 256;
static constexpr int TILE_R = 128;
static constexpr int DC = 32;
static constexpr int NC = D / DC;

__device__ float g_G[K * K];
__device__ float g_C[K * K];
__device__ float g_Vt[D * K];      // V transposed: Vt[d][k]

__device__ __forceinline__ u64 pack2(float lo, float hi) {
    u64 r;
    asm("mov.b64 %0, {%1, %2};" : "=l"(r) : "f"(lo), "f"(hi));
    return r;
}
__device__ __forceinline__ float2 unpack2(u64 v) {
    float2 r;
    asm("mov.b64 {%0, %1}, %2;" : "=f"(r.x), "=f"(r.y) : "l"(v));
    return r;
}
__device__ __forceinline__ void ffma2(u64& d, u64 a, u64 b) {
    asm("fma.rn.f32x2 %0, %1, %2, %0;" : "+l"(d) : "l"(a), "l"(b));
}
__device__ __forceinline__ void cp16cg(float* s, const float* g) {
    unsigned ss = (unsigned)__cvta_generic_to_shared(s);
    asm volatile("cp.async.cg.shared.global [%0], [%1], 16;" :: "r"(ss), "l"(g));
}
__device__ __forceinline__ void cp16ca(float* s, const float* g) {
    unsigned ss = (unsigned)__cvta_generic_to_shared(s);
    asm volatile("cp.async.ca.shared.global [%0], [%1], 16;" :: "r"(ss), "l"(g));
}
#define CP_COMMIT() asm volatile("cp.async.commit_group;" ::: "memory")
#define CP_WAIT1()  asm volatile("cp.async.wait_group 1;" ::: "memory")
#define CP_WAIT0()  asm volatile("cp.async.wait_group 0;" ::: "memory")

// ---------------- G = V V^T + build g_Vt ----------------
__global__ void gram_kernel(const float* __restrict__ V) {
    int k1 = blockIdx.x;
    int w = threadIdx.x >> 5;
    int lane = threadIdx.x & 31;
    #pragma unroll
    for (int i = 0; i < 4; i++) {
        int k2 = w * 4 + i;
        float s = 0.f;
        #pragma unroll
        for (int j = 0; j < D; j += 128) {
            float4 a = *(const float4*)(V + k1 * D + j + lane * 4);
            float4 b = *(const float4*)(V + k2 * D + j + lane * 4);
            s += a.x * b.x + a.y * b.y + a.z * b.z + a.w * b.w;
        }
        #pragma unroll
        for (int o = 16; o; o >>= 1) s += __shfl_down_sync(0xffffffffu, s, o);
        if (lane == 0) g_G[k1 * K + k2] = s;
    }
    // transpose row k1 of V into g_Vt
    for (int d = threadIdx.x; d < D; d += 256)
        g_Vt[d * K + k1] = V[k1 * D + d];
}

// ---------------- C = (I+U)^{-1} diag(beta) ----------------
__global__ void prepc_kernel() {
    __shared__ float G[K * K];
    __shared__ float beta[K];
    int t = threadIdx.x;
    for (int i = t; i < K * K; i += 32) G[i] = g_G[i];
    __syncwarp();
    beta[t] = 1.f / G[t * K + t];
    __syncwarp();
    float x[K];
    int c = t;
    for (int j = 0; j < K; j++) x[j] = 0.f;
    x[c] = 1.f;
    for (int j = c - 1; j >= 0; j--) {
        float s = 0.f;
        for (int m = j + 1; m <= c; m++) s += beta[j] * G[j * K + m] * x[m];
        x[j] = -s;
    }
    for (int j = 0; j < K; j++) g_C[j * K + c] = x[j] * beta[c];
}

// ---------------- fused: out = h - ((h V^T) C) V ----------------
__global__ __launch_bounds__(NT, 2) void fused_kernel(
    const float* __restrict__ H, const float* __restrict__ V,
    float* __restrict__ OUT)
{
    __shared__ __align__(16) float HsA[2][TILE_R * 36];  // A: H tiles; B: H source tiles
    __shared__ __align__(16) float VtA[2][DC * 36];      // A: Vt tiles;  B: Vs tiles
    __shared__ float Ps2[2 * TILE_R * 33];               // partials; slab0 -> Ws; tail -> corr
    __shared__ __align__(16) float sC[K * K];

    float* corr = Ps2 + 3840;                            // stride 36, 4608 floats (fits)

    const int t = threadIdx.x;
    const int row0 = blockIdx.x * TILE_R;

    for (int i = t; i < K * K; i += NT) sC[i] = g_C[i];

    const int rg = t & 31;          // A compute: rows rg+{0,32,64,96}
    const int kh = (t >> 5) & 1;    // A compute: k-half
    const int dq = t >> 6;          // A compute: d-quarter
    const int fr = t >> 3;          // staging/epilogue row id
    const int fc4 = t & 7;          // staging/epilogue float4 id

    // ================= Phase A (pipelined): P = H V^T =================
    u64 acc[4][8];
    #pragma unroll
    for (int j = 0; j < 4; j++)
        #pragma unroll
        for (int i = 0; i < 8; i++) acc[j][i] = 0ULL;

    auto issueA = [&](int c, int b) {
        int dc = c * DC;
        #pragma unroll
        for (int i = 0; i < 4; i++) {
            int r = i * 32 + fr;
            cp16cg(&HsA[b][r * 36 + fc4 * 4],
                   H + (size_t)(row0 + r) * D + dc + fc4 * 4);
        }
        cp16ca(&VtA[b][fr * 36 + fc4 * 4], g_Vt + (size_t)(dc + fr) * K + fc4 * 4);
    };

    issueA(0, 0);
    CP_COMMIT();
    for (int c = 0; c < NC; c++) {
        int b = c & 1;
        if (c + 1 < NC) {
            issueA(c + 1, b ^ 1);
            CP_COMMIT();
            CP_WAIT1();
        } else {
            CP_WAIT0();
        }
        __syncthreads();
        #pragma unroll
        for (int d4 = 0; d4 < 2; d4++) {
            float4 hv[4];
            #pragma unroll
            for (int j = 0; j < 4; j++) {
                int r = rg + 32 * j;
                hv[j] = *(const float4*)(&HsA[b][r * 36 + dq * 8 + d4 * 4]);
            }
            #pragma unroll
            for (int e = 0; e < 4; e++) {
                const float* vrow = &VtA[b][(dq * 8 + d4 * 4 + e) * 36 + kh * 16];
                float4 v0 = *(const float4*)(vrow);
                float4 v1 = *(const float4*)(vrow + 4);
                float4 v2 = *(const float4*)(vrow + 8);
                float4 v3 = *(const float4*)(vrow + 12);
                const u64* p0 = (const u64*)&v0;
                const u64* p1 = (const u64*)&v1;
                const u64* p2 = (const u64*)&v2;
                const u64* p3 = (const u64*)&v3;
                #pragma unroll
                for (int j = 0; j < 4; j++) {
                    float he = ((const float*)&hv[j])[e];
                    u64 hh = pack2(he, he);
                    ffma2(acc[j][0], hh, p0[0]); ffma2(acc[j][1], hh, p0[1]);
                    ffma2(acc[j][2], hh, p1[0]); ffma2(acc[j][3], hh, p1[1]);
                    ffma2(acc[j][4], hh, p2[0]); ffma2(acc[j][5], hh, p2[1]);
                    ffma2(acc[j][6], hh, p3[0]); ffma2(acc[j][7], hh, p3[1]);
                }
            }
        }
        __syncthreads();
    }

    // prefetch phase-B chunk 0 early (hidden behind reduction below)
    const int rqb = t >> 2;         // B compute rows rqb, rqb+64
    const int dqb = t & 3;          // B compute d-octet
    auto issueB = [&](int c, int b) {
        int dc = c * DC;
        cp16ca(&VtA[b][fr * 36 + fc4 * 4], V + (size_t)fr * D + dc + fc4 * 4);
        #pragma unroll
        for (int i = 0; i < 4; i++) {
            int r = i * 32 + fr;
            cp16cg(&HsA[b][r * 36 + fc4 * 4],
                   H + (size_t)(row0 + r) * D + dc + fc4 * 4);
        }
    };
    issueB(0, 0);
    CP_COMMIT();

    // ---- partials -> Ps2 (two passes over d-quarters) ----
    if (dq < 2) {
        #pragma unroll
        for (int j = 0; j < 4; j++) {
            int r = rg + 32 * j;
            float* pr = &Ps2[(dq * TILE_R + r) * 33 + kh * 16];
            #pragma unroll
            for (int i = 0; i < 8; i++) {
                float2 f = unpack2(acc[j][i]);
                pr[2 * i] = f.x;
                pr[2 * i + 1] = f.y;
            }
        }
    }
    __syncthreads();
    if (dq >= 2) {
        #pragma unroll
        for (int j = 0; j < 4; j++) {
            int r = rg + 32 * j;
            float* pr = &Ps2[((dq - 2) * TILE_R + r) * 33 + kh * 16];
            #pragma unroll
            for (int i = 0; i < 8; i++) {
                float2 f = unpack2(acc[j][i]);
                pr[2 * i] += f.x;
                pr[2 * i + 1] += f.y;
            }
        }
    }
    __syncthreads();

    // ---- W = (P0+P1) C  (Ws aliases Ps2 slab0) ----
    {
        int rt = t & 127, kh2 = t >> 7;
        float w[16];
        #pragma unroll
        for (int c2 = 0; c2 < 16; c2++) w[c2] = 0.f;
        #pragma unroll 4
        for (int j = 0; j < K; j++) {
            float pj = Ps2[rt * 33 + j] + Ps2[(TILE_R + rt) * 33 + j];
            #pragma unroll
            for (int c4 = 0; c4 < 4; c4++) {
                float4 cv = *(const float4*)(&sC[j * K + kh2 * 16 + c4 * 4]);
                w[c4 * 4 + 0] += pj * cv.x;
                w[c4 * 4 + 1] += pj * cv.y;
                w[c4 * 4 + 2] += pj * cv.z;
                w[c4 * 4 + 3] += pj * cv.w;
            }
        }
        __syncthreads();                 // all Ps2 reads done
        #pragma unroll
        for (int c2 = 0; c2 < 16; c2++) Ps2[rt * 33 + kh2 * 16 + c2] = w[c2];
    }
    __syncthreads();

    float w0[K], w1[K];
    #pragma unroll
    for (int k = 0; k < K; k++) {
        w0[k] = Ps2[rqb * 33 + k];
        w1[k] = Ps2[(rqb + 64) * 33 + k];
    }

    // ================= Phase B (pipelined): out = h - W V =================
    for (int c = 0; c < NC; c++) {
        int b = c & 1;
        if (c + 1 < NC) {
            issueB(c + 1, b ^ 1);
            CP_COMMIT();
            CP_WAIT1();
        } else {
            CP_WAIT0();
        }
        __syncthreads();                 // data ready; also orders w0/w1 reads vs corr writes
        u64 a2[2][4];
        #pragma unroll
        for (int j = 0; j < 2; j++)
            #pragma unroll
            for (int i = 0; i < 4; i++) a2[j][i] = 0ULL;
        #pragma unroll
        for (int k = 0; k < K; k++) {
            float4 va = *(const float4*)(&VtA[b][k * 36 + dqb * 8]);
            float4 vb = *(const float4*)(&VtA[b][k * 36 + dqb * 8 + 4]);
            const u64* vpa = (const u64*)&va;
            const u64* vpb = (const u64*)&vb;
            u64 ww0 = pack2(w0[k], w0[k]);
            u64 ww1 = pack2(w1[k], w1[k]);
            ffma2(a2[0][0], ww0, vpa[0]); ffma2(a2[0][1], ww0, vpa[1]);
            ffma2(a2[0][2], ww0, vpb[0]); ffma2(a2[0][3], ww0, vpb[1]);
            ffma2(a2[1][0], ww1, vpa[0]); ffma2(a2[1][1], ww1, vpa[1]);
            ffma2(a2[1][2], ww1, vpb[0]); ffma2(a2[1][3], ww1, vpb[1]);
        }
        #pragma unroll
        for (int j = 0; j < 2; j++) {
            int r = rqb + 64 * j;
            float2 p0 = unpack2(a2[j][0]);
            float2 p1 = unpack2(a2[j][1]);
            float2 p2 = unpack2(a2[j][2]);
            float2 p3 = unpack2(a2[j][3]);
            float4 ca = {p0.x, p0.y, p1.x, p1.y};
            float4 cb = {p2.x, p2.y, p3.x, p3.y};
            *(float4*)(&corr[r * 36 + dqb * 8]) = ca;
            *(float4*)(&corr[r * 36 + dqb * 8 + 4]) = cb;
        }
        __syncthreads();
        #pragma unroll
        for (int i = 0; i < 4; i++) {
            int r = i * 32 + fr;
            float4 hv = *(const float4*)(&HsA[b][r * 36 + fc4 * 4]);
            float4 cr = *(const float4*)(&corr[r * 36 + fc4 * 4]);
            float4 o = {hv.x - cr.x, hv.y - cr.y, hv.z - cr.z, hv.w - cr.w};
            *(float4*)(OUT + (size_t)(row0 + i * 32 + fr) * D + c * DC + fc4 * 4) = o;
        }
        __syncthreads();                 // guard buffer + corr reuse
    }
}

extern "C" void kernel_launch(void* const* d_in, const int* in_sizes, int n_in,
                              void* d_out, int out_size) {
    const float* H = (const float*)d_in[0];
    const float* V = (const float*)d_in[1];
    float* OUT = (float*)d_out;
    const int N = in_sizes[0] / D;

    gram_kernel<<<K, 256>>>(V);
    prepc_kernel<<<1, 32>>>();
    fused_kernel<<<N / TILE_R, NT>>>(H, V, OUT);
}

// round 9
// speedup vs baseline: 2.6067x; 1.2075x over previous
#include <cuda_runtime.h>
#include <cstdint>

typedef unsigned int u32;

static constexpr int D = 1024;
static constexpr int K = 32;
static constexpr int NT = 256;       // 8 warps
static constexpr int TILE_R = 128;   // rows per block
static constexpr int DC = 32;        // d per chunk
static constexpr int NCH = D / DC;   // 32

// smem float offsets
static constexpr int HS0 = 0;        // 128*36 = 4608   (phase A H buf 0; later W)
static constexpr int HS1 = 4608;     // 128*36 = 4608   (phase A H buf 1; later P)
static constexpr int VB0 = 9216;     // 32*40 = 1280    (V tile buf 0)
static constexpr int VB1 = 10496;    // 32*40 = 1280    (V tile buf 1)
static constexpr int SCO = 11776;    // 32*32 = 1024    (C)
static constexpr int SM_FLOATS = 12800;                 // 51200 B

__device__ float g_G[K * K];
__device__ float g_C[K * K];
__device__ float g_Vt[D * K];        // Vt[d][k]

__device__ __forceinline__ u32 tf32r(float x) {
    u32 r;
    asm("cvt.rna.tf32.f32 %0, %1;" : "=r"(r) : "f"(x));
    return r;
}
__device__ __forceinline__ void mma_tf32(float* d, u32 a0, u32 a1, u32 a2, u32 a3,
                                         u32 b0, u32 b1) {
    asm volatile("mma.sync.aligned.m16n8k8.row.col.f32.tf32.tf32.f32 "
        "{%0,%1,%2,%3}, {%4,%5,%6,%7}, {%8,%9}, {%0,%1,%2,%3};"
        : "+f"(d[0]), "+f"(d[1]), "+f"(d[2]), "+f"(d[3])
        : "r"(a0), "r"(a1), "r"(a2), "r"(a3), "r"(b0), "r"(b1));
}
__device__ __forceinline__ void cp16(float* s, const float* g) {
    u32 ss = (u32)__cvta_generic_to_shared(s);
    asm volatile("cp.async.cg.shared.global [%0], [%1], 16;" :: "r"(ss), "l"(g) : "memory");
}
#define CP_COMMIT() asm volatile("cp.async.commit_group;" ::: "memory")
#define CP_WAIT1()  asm volatile("cp.async.wait_group 1;" ::: "memory")
#define CP_WAIT0()  asm volatile("cp.async.wait_group 0;" ::: "memory")

// ---------------- G = V V^T + build g_Vt ----------------
__global__ void gram_kernel(const float* __restrict__ V) {
    int k1 = blockIdx.x;
    int w = threadIdx.x >> 5;
    int lane = threadIdx.x & 31;
    #pragma unroll
    for (int i = 0; i < 4; i++) {
        int k2 = w * 4 + i;
        float s = 0.f;
        #pragma unroll
        for (int j = 0; j < D; j += 128) {
            float4 a = *(const float4*)(V + k1 * D + j + lane * 4);
            float4 b = *(const float4*)(V + k2 * D + j + lane * 4);
            s += a.x * b.x + a.y * b.y + a.z * b.z + a.w * b.w;
        }
        #pragma unroll
        for (int o = 16; o; o >>= 1) s += __shfl_down_sync(0xffffffffu, s, o);
        if (lane == 0) g_G[k1 * K + k2] = s;
    }
    for (int d = threadIdx.x; d < D; d += 256)
        g_Vt[d * K + k1] = V[k1 * D + d];
}

// ---------------- C = (I+U)^{-1} diag(beta) ----------------
__global__ void prepc_kernel() {
    __shared__ float G[K * K];
    __shared__ float beta[K];
    int t = threadIdx.x;
    for (int i = t; i < K * K; i += 32) G[i] = g_G[i];
    __syncwarp();
    beta[t] = 1.f / G[t * K + t];
    __syncwarp();
    float x[K];
    int c = t;
    for (int j = 0; j < K; j++) x[j] = 0.f;
    x[c] = 1.f;
    for (int j = c - 1; j >= 0; j--) {
        float s = 0.f;
        for (int m = j + 1; m <= c; m++) s += beta[j] * G[j * K + m] * x[m];
        x[j] = -s;
    }
    for (int j = 0; j < K; j++) g_C[j * K + c] = x[j] * beta[c];
}

// ---------------- fused: out = h - ((h V^T) C) V, tf32 mma.sync ----------------
__global__ __launch_bounds__(NT, 4) void fused_kernel(
    const float* __restrict__ H, const float* __restrict__ V,
    float* __restrict__ OUT)
{
    __shared__ __align__(16) float sm[SM_FLOATS];

    const int t = threadIdx.x;
    const int wid = t >> 5;
    const int lid = t & 31;
    const int g = lid >> 2;          // fragment row group 0..7
    const int tq = lid & 3;          // fragment thread-in-group 0..3
    const int w16 = wid * 16;        // warp's row base
    const int row0 = blockIdx.x * TILE_R;

    for (int i = t; i < K * K; i += NT) sm[SCO + i] = g_C[i];

    // staging ids: fr = row/4-group, fc = float4 col
    const int fc = t & 7;

    auto stageH = [&](int c, int b) {       // H tile 128x32, stride 36
        float* dst = sm + (b ? HS1 : HS0);
        int dc = c * DC;
        #pragma unroll
        for (int i = 0; i < 4; i++) {
            int seg = i * 256 + t, r = seg >> 3, c16 = seg & 7;
            cp16(dst + r * 36 + c16 * 4, H + (size_t)(row0 + r) * D + dc + c16 * 4);
        }
    };
    auto stageVt = [&](int c, int b) {      // Vt tile 32(d)x32(k), stride 40
        float* dst = sm + (b ? VB1 : VB0);
        int r = t >> 3;
        cp16(dst + r * 40 + fc * 4, g_Vt + (size_t)(c * DC + r) * K + fc * 4);
    };
    auto stageVs = [&](int c, int b) {      // Vs tile 32(k)x32(d), stride 40
        float* dst = sm + (b ? VB1 : VB0);
        int r = t >> 3;
        cp16(dst + r * 40 + fc * 4, V + (size_t)r * D + c * DC + fc * 4);
    };

    // ============ Phase A: P = H V^T ============
    float pacc[4][4];
    #pragma unroll
    for (int nt = 0; nt < 4; nt++)
        #pragma unroll
        for (int i = 0; i < 4; i++) pacc[nt][i] = 0.f;

    stageH(0, 0); stageVt(0, 0); CP_COMMIT();
    for (int c = 0; c < NCH; c++) {
        int b = c & 1;
        if (c + 1 < NCH) {
            stageH(c + 1, b ^ 1); stageVt(c + 1, b ^ 1);
            CP_COMMIT(); CP_WAIT1();
        } else CP_WAIT0();
        __syncthreads();
        const float* hs = sm + (b ? HS1 : HS0);
        const float* vt = sm + (b ? VB1 : VB0);
        #pragma unroll
        for (int ks = 0; ks < 4; ks++) {
            int d0 = ks * 8;
            u32 a0 = tf32r(hs[(w16 + g) * 36 + d0 + tq]);
            u32 a1 = tf32r(hs[(w16 + g + 8) * 36 + d0 + tq]);
            u32 a2 = tf32r(hs[(w16 + g) * 36 + d0 + tq + 4]);
            u32 a3 = tf32r(hs[(w16 + g + 8) * 36 + d0 + tq + 4]);
            #pragma unroll
            for (int nt = 0; nt < 4; nt++) {
                u32 b0 = tf32r(vt[(d0 + tq) * 40 + nt * 8 + g]);
                u32 b1 = tf32r(vt[(d0 + tq + 4) * 40 + nt * 8 + g]);
                mma_tf32(pacc[nt], a0, a1, a2, a3, b0, b1);
            }
        }
        __syncthreads();
    }

    // prefetch phase-B V chunk 0 (Vb[0] free: last A chunk used Vb[1])
    stageVs(0, 0); CP_COMMIT();

    // write P (stride 33) into HS1 region
    {
        float* P = sm + HS1;
        #pragma unroll
        for (int nt = 0; nt < 4; nt++) {
            int cc = nt * 8 + 2 * tq;
            P[(w16 + g) * 33 + cc] = pacc[nt][0];
            P[(w16 + g) * 33 + cc + 1] = pacc[nt][1];
            P[(w16 + g + 8) * 33 + cc] = pacc[nt][2];
            P[(w16 + g + 8) * 33 + cc + 1] = pacc[nt][3];
        }
    }
    __syncthreads();

    // W = P C (CUDA cores), write stride 36 into HS0 region
    {
        const float* P = sm + HS1;
        const float* sC = sm + SCO;
        float* W = sm + HS0;
        int r = t & 127, half = t >> 7;
        float wv[16];
        #pragma unroll
        for (int i = 0; i < 16; i++) wv[i] = 0.f;
        #pragma unroll 4
        for (int j = 0; j < K; j++) {
            float pj = P[r * 33 + j];
            #pragma unroll
            for (int c4 = 0; c4 < 4; c4++) {
                float4 cv = *(const float4*)(&sC[j * K + half * 16 + c4 * 4]);
                wv[c4 * 4 + 0] += pj * cv.x;
                wv[c4 * 4 + 1] += pj * cv.y;
                wv[c4 * 4 + 2] += pj * cv.z;
                wv[c4 * 4 + 3] += pj * cv.w;
            }
        }
        #pragma unroll
        for (int i = 0; i < 16; i++) W[r * 36 + half * 16 + i] = wv[i];
    }
    __syncthreads();

    // hoist W a-fragments (constant across all phase-B chunks)
    u32 wa[4][4];
    {
        const float* W = sm + HS0;
        #pragma unroll
        for (int ks = 0; ks < 4; ks++) {
            int k0 = ks * 8;
            wa[ks][0] = tf32r(W[(w16 + g) * 36 + k0 + tq]);
            wa[ks][1] = tf32r(W[(w16 + g + 8) * 36 + k0 + tq]);
            wa[ks][2] = tf32r(W[(w16 + g) * 36 + k0 + tq + 4]);
            wa[ks][3] = tf32r(W[(w16 + g + 8) * 36 + k0 + tq + 4]);
        }
    }

    // ============ Phase B: out = h - W V ============
    for (int c = 0; c < NCH; c++) {
        int b = c & 1;
        if (c + 1 < NCH) {
            stageVs(c + 1, b ^ 1);
            CP_COMMIT(); CP_WAIT1();
        } else CP_WAIT0();
        __syncthreads();
        const float* vs = sm + (b ? VB1 : VB0);
        int dc = c * DC;
        #pragma unroll
        for (int nt = 0; nt < 4; nt++) {
            float acc[4] = {0.f, 0.f, 0.f, 0.f};
            #pragma unroll
            for (int ks = 0; ks < 4; ks++) {
                u32 b0 = tf32r(vs[(ks * 8 + tq) * 40 + nt * 8 + g]);
                u32 b1 = tf32r(vs[(ks * 8 + tq + 4) * 40 + nt * 8 + g]);
                mma_tf32(acc, wa[ks][0], wa[ks][1], wa[ks][2], wa[ks][3], b0, b1);
            }
            size_t r0g = (size_t)(row0 + w16 + g) * D + dc + nt * 8 + 2 * tq;
            size_t r1g = r0g + (size_t)8 * D;
            float2 h0 = *(const float2*)(H + r0g);
            float2 h1 = *(const float2*)(H + r1g);
            float2 o0 = {h0.x - acc[0], h0.y - acc[1]};
            float2 o1 = {h1.x - acc[2], h1.y - acc[3]};
            *(float2*)(OUT + r0g) = o0;
            *(float2*)(OUT + r1g) = o1;
        }
        __syncthreads();
    }
}

extern "C" void kernel_launch(void* const* d_in, const int* in_sizes, int n_in,
                              void* d_out, int out_size) {
    const float* H = (const float*)d_in[0];
    const float* V = (const float*)d_in[1];
    float* OUT = (float*)d_out;
    const int N = in_sizes[0] / D;

    gram_kernel<<<K, 256>>>(V);
    prepc_kernel<<<1, 32>>>();
    fused_kernel<<<N / TILE_R, NT>>>(H, V, OUT);
}